// round 8
// baseline (speedup 1.0000x reference)
#include <cuda_runtime.h>
#include <math.h>

#define BB 32
#define HH 32
#define KVHH 8
#define DD 128
#define GG 4
#define BLK_SZ 16
#define MAX_BLOCKS 128
#define NSPLIT 8
#define NWARP 8
#define NTHREADS 256

// Scratch (allocation-free: __device__ globals)
__device__ float g_pacc[BB * KVHH * NSPLIT * GG * DD];  // 4 MB split partials
__device__ float g_pl[BB * KVHH * NSPLIT * GG];
__device__ float g_qrot[BB * HH * DD];    // RoPE'd q, scale folded
__device__ float g_krot[BB * KVHH * DD];  // RoPE'd new k

// ---------------- prep: sincos once per (b,d), reused across 40 heads ----------------
__global__ __launch_bounds__(DD) void rope_prep_kernel(
    const float* __restrict__ query,
    const float* __restrict__ key,
    const int*   __restrict__ context_lens)
{
    const int b = blockIdx.x;   // 32 blocks
    const int d = threadIdx.x;  // 128 threads

    __shared__ float cs[DD], sn[DD];
    const float pos = (float)context_lens[b];
    const int fi = d & 63;
    const float inv = exp2f(-(float)fi * 0.2076205092783674f);  // log2(10000)/64
    float s, c;
    sincosf(pos * inv, &s, &c);
    cs[d] = c; sn[d] = s;
    __syncthreads();

    const float myc = cs[d], mys = sn[d];
    const int dofs = (d < 64) ? (d + 64) : (d - 64);
    const float sgn = (d < 64) ? -1.f : 1.f;

#pragma unroll 4
    for (int h = 0; h < HH; h++) {
        const float* base = query + ((long)b * HH + h) * DD;
        float x = base[d];
        float other = sgn * base[dofs];
        g_qrot[((long)b * HH + h) * DD + d] =
            (x * myc + other * mys) * 0.08838834764831845f;  // D^-0.5
    }
#pragma unroll
    for (int kh = 0; kh < KVHH; kh++) {
        const float* base = key + ((long)b * KVHH + kh) * DD;
        float x = base[d];
        float other = sgn * base[dofs];
        g_krot[((long)b * KVHH + kh) * DD + d] = x * myc + other * mys;
    }
}

// ---------- 6-SHFL fold: lane L ends with FULL score of head (L&3) ----------
__device__ __forceinline__ float fold4(float s0, float s1, float s2, float s3, int lane) {
    bool b0 = lane & 1;
    float a01 = b0 ? s1 : s0, o01 = b0 ? s0 : s1;
    a01 += __shfl_xor_sync(0xffffffffu, o01, 1);
    float a23 = b0 ? s3 : s2, o23 = b0 ? s2 : s3;
    a23 += __shfl_xor_sync(0xffffffffu, o23, 1);
    bool b1 = lane & 2;
    float v = b1 ? a23 : a01, o = b1 ? a01 : a23;
    v += __shfl_xor_sync(0xffffffffu, o, 2);
    v += __shfl_xor_sync(0xffffffffu, v, 4);
    v += __shfl_xor_sync(0xffffffffu, v, 8);
    v += __shfl_xor_sync(0xffffffffu, v, 16);
    return v;
}

// ------- per-token update: no online max, fold4 reduce, 1 exp/lane -------
__device__ __forceinline__ void upd_token(
    const float4& kv, const float4& vv,
    const float4 qv[GG], float& l_own, float4 acc[GG], int lane)
{
    float sc[GG];
#pragma unroll
    for (int g = 0; g < GG; g++)
        sc[g] = kv.x * qv[g].x + kv.y * qv[g].y + kv.z * qv[g].z + kv.w * qv[g].w;
    float s = fold4(sc[0], sc[1], sc[2], sc[3], lane);
    float p = __expf(s);          // score of head (lane&3)
    l_own += p;
    float p0 = __shfl_sync(0xffffffffu, p, 0);
    float p1 = __shfl_sync(0xffffffffu, p, 1);
    float p2 = __shfl_sync(0xffffffffu, p, 2);
    float p3 = __shfl_sync(0xffffffffu, p, 3);
    acc[0].x += p0 * vv.x; acc[0].y += p0 * vv.y; acc[0].z += p0 * vv.z; acc[0].w += p0 * vv.w;
    acc[1].x += p1 * vv.x; acc[1].y += p1 * vv.y; acc[1].z += p1 * vv.z; acc[1].w += p1 * vv.w;
    acc[2].x += p2 * vv.x; acc[2].y += p2 * vv.y; acc[2].z += p2 * vv.z; acc[2].w += p2 * vv.w;
    acc[3].x += p3 * vv.x; acc[3].y += p3 * vv.y; acc[3].z += p3 * vv.z; acc[3].w += p3 * vv.w;
}

// ---------------- split flash-decode (R7 skeleton) ----------------
__global__ __launch_bounds__(NTHREADS) void pa_split_kernel(
    const float* __restrict__ value,
    const float* __restrict__ k_cache,
    const float* __restrict__ v_cache,
    const int*   __restrict__ block_table,
    const int*   __restrict__ context_lens)
{
    const int split = blockIdx.x;
    const int kvh   = blockIdx.y;
    const int b     = blockIdx.z;
    const int tid   = threadIdx.x;
    const int lane  = tid & 31;
    const int w     = tid >> 5;

    const int ctx   = context_lens[b];
    const int chunk = (ctx + NSPLIT - 1) / NSPLIT;
    const int s0    = split * chunk;
    const int s1    = min(s0 + chunk, ctx);
    const int last  = ctx - 1;
    const int end   = min(s1, last);   // hot loop excludes the in-flight token

    __shared__ int   btab[MAX_BLOCKS];
    __shared__ float wl[NWARP][GG];
    __shared__ float wacc[NWARP][GG][DD];

    for (int i = tid; i < MAX_BLOCKS; i += NTHREADS)
        btab[i] = block_table[b * MAX_BLOCKS + i];
    __syncthreads();

    float4 qv[GG];
#pragma unroll
    for (int g = 0; g < GG; g++)
        qv[g] = *(const float4*)&g_qrot[((long)b * HH + kvh * GG + g) * DD + lane * 4];

    float l_own = 0.f;
    float4 acc[GG];
#pragma unroll
    for (int g = 0; g < GG; g++)
        acc[g].x = acc[g].y = acc[g].z = acc[g].w = 0.f;

    const unsigned hoff = (unsigned)kvh * DD + lane * 4;

    int s = s0 + w;
    // 4x unrolled, unconditional batched loads (MLP=8 per warp)
    while (s + 3 * NWARP < end) {
        unsigned o0, o1, o2, o3;
        {
            int t0 = s, t1 = s + NWARP, t2 = s + 2 * NWARP, t3 = s + 3 * NWARP;
            o0 = (((unsigned)btab[t0 >> 4] * BLK_SZ + (t0 & 15)) * (KVHH * DD)) + hoff;
            o1 = (((unsigned)btab[t1 >> 4] * BLK_SZ + (t1 & 15)) * (KVHH * DD)) + hoff;
            o2 = (((unsigned)btab[t2 >> 4] * BLK_SZ + (t2 & 15)) * (KVHH * DD)) + hoff;
            o3 = (((unsigned)btab[t3 >> 4] * BLK_SZ + (t3 & 15)) * (KVHH * DD)) + hoff;
        }
        float4 k0 = *(const float4*)(k_cache + o0);
        float4 v0 = *(const float4*)(v_cache + o0);
        float4 k1 = *(const float4*)(k_cache + o1);
        float4 v1 = *(const float4*)(v_cache + o1);
        float4 k2 = *(const float4*)(k_cache + o2);
        float4 v2 = *(const float4*)(v_cache + o2);
        float4 k3 = *(const float4*)(k_cache + o3);
        float4 v3 = *(const float4*)(v_cache + o3);

        upd_token(k0, v0, qv, l_own, acc, lane);
        upd_token(k1, v1, qv, l_own, acc, lane);
        upd_token(k2, v2, qv, l_own, acc, lane);
        upd_token(k3, v3, qv, l_own, acc, lane);
        s += 4 * NWARP;
    }
    while (s < end) {
        unsigned off = (((unsigned)btab[s >> 4] * BLK_SZ + (s & 15)) * (KVHH * DD)) + hoff;
        float4 kv = *(const float4*)(k_cache + off);
        float4 vv = *(const float4*)(v_cache + off);
        upd_token(kv, vv, qv, l_own, acc, lane);
        s += NWARP;
    }

    // in-flight token (RoPE'd new k from scratch, new v from input)
    if (last >= s0 && last < s1 && w == ((last - s0) % NWARP)) {
        float4 kv = *(const float4*)&g_krot[((long)b * KVHH + kvh) * DD + lane * 4];
        float4 vv = *(const float4*)(value + ((long)b * KVHH + kvh) * DD + lane * 4);
        upd_token(kv, vv, qv, l_own, acc, lane);
    }

    // stash per-warp partials (l_own at lane g is head g's sum)
#pragma unroll
    for (int g = 0; g < GG; g++)
        *(float4*)&wacc[w][g][lane * 4] = acc[g];
    if (lane < GG) wl[w][lane] = l_own;
    __syncthreads();

    const long pbase = ((long)(b * KVHH + kvh) * NSPLIT + split) * GG;
    for (int i = tid; i < GG * DD; i += NTHREADS) {
        int g = i >> 7, d = i & 127;
        float t = 0.f;
#pragma unroll
        for (int ww = 0; ww < NWARP; ww++) t += wacc[ww][g][d];
        g_pacc[(pbase + g) * DD + d] = t;
    }
    if (tid < GG) {
        float L = 0.f;
#pragma unroll
        for (int ww = 0; ww < NWARP; ww++) L += wl[ww][tid];
        g_pl[pbase + tid] = L;
    }
}

// ---------------- combine (plain sums) ----------------
__global__ __launch_bounds__(DD) void pa_combine_kernel(float* __restrict__ out) {
    const int idx = blockIdx.x;             // B*KVH*G
    const int g   = idx % GG;
    const int kvh = (idx / GG) % KVHH;
    const int b   = idx / (GG * KVHH);
    const int d   = threadIdx.x;

    const long base = ((long)(b * KVHH + kvh) * NSPLIT) * GG + g;
    float L = 0.f, o = 0.f;
#pragma unroll
    for (int s = 0; s < NSPLIT; s++) {
        L += g_pl[base + (long)s * GG];
        o += g_pacc[(base + (long)s * GG) * DD + d];
    }
    out[((long)b * HH + kvh * GG + g) * DD + d] = o / L;
}

extern "C" void kernel_launch(void* const* d_in, const int* in_sizes, int n_in,
                              void* d_out, int out_size) {
    const float* query  = (const float*)d_in[0];
    const float* key    = (const float*)d_in[1];
    const float* value  = (const float*)d_in[2];
    const float* k_cache = (const float*)d_in[3];
    const float* v_cache = (const float*)d_in[4];
    const int*   block_table  = (const int*)d_in[5];
    const int*   context_lens = (const int*)d_in[6];
    float* out = (float*)d_out;

    rope_prep_kernel<<<BB, DD>>>(query, key, context_lens);

    dim3 grid(NSPLIT, KVHH, BB);
    pa_split_kernel<<<grid, NTHREADS>>>(value, k_cache, v_cache,
                                        block_table, context_lens);
    pa_combine_kernel<<<BB * KVHH * GG, DD>>>(out);
}

// round 9
// speedup vs baseline: 1.0238x; 1.0238x over previous
#include <cuda_runtime.h>
#include <math.h>

#define BB 32
#define HH 32
#define KVHH 8
#define DD 128
#define GG 4
#define BLK_SZ 16
#define MAX_BLOCKS 128
#define NSPLIT 8
#define NWARP 8
#define NTHREADS 256

// Scratch (allocation-free: __device__ globals)
__device__ float g_pacc[BB * KVHH * NSPLIT * GG * DD];  // 4 MB split partials
__device__ float g_pl[BB * KVHH * NSPLIT * GG];

// ------- per-token update (R7-proven): no online max, butterfly reduce -------
__device__ __forceinline__ void upd_token(
    const float4& kv, const float4& vv,
    const float4 qv[GG], float l[GG], float4 acc[GG])
{
    float sc[GG];
#pragma unroll
    for (int g = 0; g < GG; g++)
        sc[g] = kv.x * qv[g].x + kv.y * qv[g].y + kv.z * qv[g].z + kv.w * qv[g].w;
#pragma unroll
    for (int off = 16; off > 0; off >>= 1) {
#pragma unroll
        for (int g = 0; g < GG; g++)
            sc[g] += __shfl_xor_sync(0xffffffffu, sc[g], off);
    }
#pragma unroll
    for (int g = 0; g < GG; g++) {
        float p = __expf(sc[g]);
        l[g] += p;
        acc[g].x += p * vv.x;
        acc[g].y += p * vv.y;
        acc[g].z += p * vv.z;
        acc[g].w += p * vv.w;
    }
}

// ---------------- split flash-decode with fused RoPE prologue ----------------
__global__ __launch_bounds__(NTHREADS) void pa_split_kernel(
    const float* __restrict__ query,
    const float* __restrict__ key,
    const float* __restrict__ value,
    const float* __restrict__ k_cache,
    const float* __restrict__ v_cache,
    const int*   __restrict__ block_table,
    const int*   __restrict__ context_lens)
{
    const int split = blockIdx.x;
    const int kvh   = blockIdx.y;
    const int b     = blockIdx.z;
    const int tid   = threadIdx.x;
    const int lane  = tid & 31;
    const int w     = tid >> 5;

    const int ctx   = context_lens[b];
    const int chunk = (ctx + NSPLIT - 1) / NSPLIT;
    const int s0    = split * chunk;
    const int s1    = min(s0 + chunk, ctx);
    const int last  = ctx - 1;
    const int end   = min(s1, last);   // hot loop excludes the in-flight token

    __shared__ int   btab[MAX_BLOCKS];
    __shared__ float wl[NWARP][GG];
    __shared__ float wacc[NWARP][GG][DD];
    __shared__ float cs[DD], sn[DD];
    __shared__ float q_s[GG][DD];
    __shared__ float krot_s[DD];

    for (int i = tid; i < MAX_BLOCKS; i += NTHREADS)
        btab[i] = block_table[b * MAX_BLOCKS + i];

    // --- fused RoPE prologue: sincos once per (b,d) into smem ---
    if (tid < DD) {
        const int fi = tid & 63;
        const float inv = exp2f(-(float)fi * 0.2076205092783674f);  // log2(10000)/64
        float s, c;
        sincosf((float)ctx * inv, &s, &c);
        cs[tid] = c; sn[tid] = s;
    }
    __syncthreads();

    // RoPE-apply 4 q rows (scale folded) + 1 k row
    for (int i = tid; i < GG * DD; i += NTHREADS) {
        int g = i >> 7, d = i & 127;
        const float* base = query + ((long)b * HH + kvh * GG + g) * DD;
        float x = base[d];
        float other = (d < 64) ? -base[d + 64] : base[d - 64];
        q_s[g][d] = (x * cs[d] + other * sn[d]) * 0.08838834764831845f;  // D^-0.5
    }
    if (tid < DD) {
        const float* base = key + ((long)b * KVHH + kvh) * DD;
        float x = base[tid];
        float other = (tid < 64) ? -base[tid + 64] : base[tid - 64];
        krot_s[tid] = x * cs[tid] + other * sn[tid];
    }
    __syncthreads();

    float4 qv[GG];
#pragma unroll
    for (int g = 0; g < GG; g++)
        qv[g] = *(const float4*)&q_s[g][lane * 4];

    float l[GG];
    float4 acc[GG];
#pragma unroll
    for (int g = 0; g < GG; g++) {
        l[g] = 0.f;
        acc[g].x = acc[g].y = acc[g].z = acc[g].w = 0.f;
    }

    const unsigned hoff = (unsigned)kvh * DD + lane * 4;

    int s = s0 + w;
    // 4x unrolled, unconditional batched loads (MLP=8 per warp)
    while (s + 3 * NWARP < end) {
        unsigned o0, o1, o2, o3;
        {
            int t0 = s, t1 = s + NWARP, t2 = s + 2 * NWARP, t3 = s + 3 * NWARP;
            o0 = (((unsigned)btab[t0 >> 4] * BLK_SZ + (t0 & 15)) * (KVHH * DD)) + hoff;
            o1 = (((unsigned)btab[t1 >> 4] * BLK_SZ + (t1 & 15)) * (KVHH * DD)) + hoff;
            o2 = (((unsigned)btab[t2 >> 4] * BLK_SZ + (t2 & 15)) * (KVHH * DD)) + hoff;
            o3 = (((unsigned)btab[t3 >> 4] * BLK_SZ + (t3 & 15)) * (KVHH * DD)) + hoff;
        }
        float4 k0 = *(const float4*)(k_cache + o0);
        float4 v0 = *(const float4*)(v_cache + o0);
        float4 k1 = *(const float4*)(k_cache + o1);
        float4 v1 = *(const float4*)(v_cache + o1);
        float4 k2 = *(const float4*)(k_cache + o2);
        float4 v2 = *(const float4*)(v_cache + o2);
        float4 k3 = *(const float4*)(k_cache + o3);
        float4 v3 = *(const float4*)(v_cache + o3);

        upd_token(k0, v0, qv, l, acc);
        upd_token(k1, v1, qv, l, acc);
        upd_token(k2, v2, qv, l, acc);
        upd_token(k3, v3, qv, l, acc);
        s += 4 * NWARP;
    }
    while (s < end) {
        unsigned off = (((unsigned)btab[s >> 4] * BLK_SZ + (s & 15)) * (KVHH * DD)) + hoff;
        float4 kv = *(const float4*)(k_cache + off);
        float4 vv = *(const float4*)(v_cache + off);
        upd_token(kv, vv, qv, l, acc);
        s += NWARP;
    }

    // in-flight token (RoPE'd new k from smem, new v from input)
    if (last >= s0 && last < s1 && w == ((last - s0) % NWARP)) {
        float4 kv = *(const float4*)&krot_s[lane * 4];
        float4 vv = *(const float4*)(value + ((long)b * KVHH + kvh) * DD + lane * 4);
        upd_token(kv, vv, qv, l, acc);
    }

    // stash per-warp partials (plain sums)
#pragma unroll
    for (int g = 0; g < GG; g++) {
        if (lane == 0) wl[w][g] = l[g];
        *(float4*)&wacc[w][g][lane * 4] = acc[g];
    }
    __syncthreads();

    const long pbase = ((long)(b * KVHH + kvh) * NSPLIT + split) * GG;
    for (int i = tid; i < GG * DD; i += NTHREADS) {
        int g = i >> 7, d = i & 127;
        float t = 0.f;
#pragma unroll
        for (int ww = 0; ww < NWARP; ww++) t += wacc[ww][g][d];
        g_pacc[(pbase + g) * DD + d] = t;
    }
    if (tid < GG) {
        float L = 0.f;
#pragma unroll
        for (int ww = 0; ww < NWARP; ww++) L += wl[ww][tid];
        g_pl[pbase + tid] = L;
    }
}

// ---------------- combine (plain sums) ----------------
__global__ __launch_bounds__(DD) void pa_combine_kernel(float* __restrict__ out) {
    const int idx = blockIdx.x;             // B*KVH*G
    const int g   = idx % GG;
    const int kvh = (idx / GG) % KVHH;
    const int b   = idx / (GG * KVHH);
    const int d   = threadIdx.x;

    const long base = ((long)(b * KVHH + kvh) * NSPLIT) * GG + g;
    float L = 0.f, o = 0.f;
#pragma unroll
    for (int s = 0; s < NSPLIT; s++) {
        L += g_pl[base + (long)s * GG];
        o += g_pacc[(base + (long)s * GG) * DD + d];
    }
    out[((long)b * HH + kvh * GG + g) * DD + d] = o / L;
}

extern "C" void kernel_launch(void* const* d_in, const int* in_sizes, int n_in,
                              void* d_out, int out_size) {
    const float* query  = (const float*)d_in[0];
    const float* key    = (const float*)d_in[1];
    const float* value  = (const float*)d_in[2];
    const float* k_cache = (const float*)d_in[3];
    const float* v_cache = (const float*)d_in[4];
    const int*   block_table  = (const int*)d_in[5];
    const int*   context_lens = (const int*)d_in[6];
    float* out = (float*)d_out;

    dim3 grid(NSPLIT, KVHH, BB);
    pa_split_kernel<<<grid, NTHREADS>>>(query, key, value, k_cache, v_cache,
                                        block_table, context_lens);
    pa_combine_kernel<<<BB * KVHH * GG, DD>>>(out);
}